// round 12
// baseline (speedup 1.0000x reference)
#include <cuda_runtime.h>
#include <cstdint>

// QORNN: B=256, T=1024, I=64, H=256, O=16
// Exact integer reformulation (bit-exact vs reference; rel_err 0.0 R2-R9):
//   x_q  = clip(rint(x*128), -128, 127)          int8, scale 1/128
//   W*_q = clip(rint(W*8), -8, 7)                int4-valued int8, scale 1/8
//   z    = (xq@Wiq + hq@Wrq) / 1024              int32 accum, exact in fp32 grid
//   m = relu(|z|+b); h_q = clip(rint(sign(z)*m*128), -128, 127)
// R10: tensor-core scan. mma.sync.m16n8k32.s8 (IMMA): one CTA = 8 batch rows
// (the mma's N dimension), 256 threads, grid 32, 1 CTA/SM. Warp w owns units
// [32w,32w+32): Wr/Wi A-fragments live in registers (80 words). h/x B-frags
// come from SMEM with padded row strides (h:68 words, x:20) -> conflict-free
// across the 8 n-columns. ~40 mma+LDS per warp-step replaces ~640 dp4a.

#define TT 1024
#define NB 256
#define HH 256
#define NI 64
#define NO 16

#define HSTR 68        // h row stride in words (4n-bank pattern, conflict-free)
#define XSTR 20        // x row stride in words

#define NWR (HH * 64)
#define NWI (HH * 16)
#define NWO (NO * 64)
#define NPACK (NWR + NWI + NWO)  // 21504 = 84 * 256

__device__ uint32_t g_WiP[NWI];
__device__ uint32_t g_WrP[NWR];
__device__ uint32_t g_WoP[NWO];

__device__ __forceinline__ int clampi(int v, int lo, int hi) {
    return v < lo ? lo : (v > hi ? hi : v);
}

__device__ __forceinline__ uint32_t pack4(const float* p) {
    uint32_t w = 0;
#pragma unroll
    for (int j = 0; j < 4; j++) {
        int q = clampi((int)rintf(p[j] * 8.0f), -8, 7);
        w |= ((uint32_t)(uint8_t)(int8_t)q) << (8 * j);
    }
    return w;
}

__global__ __launch_bounds__(256)
void prep_kernel(const float* __restrict__ Wi,
                 const float* __restrict__ Wr,
                 const float* __restrict__ Wo) {
    int i = blockIdx.x * 256 + threadIdx.x;
    if (i < NWR) {
        int row = i >> 6, kw = i & 63;
        g_WrP[i] = pack4(Wr + row * HH + kw * 4);
    } else if (i < NWR + NWI) {
        int j = i - NWR;
        int row = j >> 4, kw = j & 15;
        g_WiP[j] = pack4(Wi + row * NI + kw * 4);
    } else if (i < NPACK) {
        int j = i - NWR - NWI;
        int row = j >> 6, kw = j & 63;
        g_WoP[j] = pack4(Wo + row * HH + kw * 4);
    }
}

// int8 quantize, round-half-even via magic add (exact: v*128 is pow2 scale).
__device__ __forceinline__ int quant8(float v) {
    float tm = fmaf(v, 128.0f, 12582912.0f);        // 2^23 + 2^22
    int q = __float_as_int(tm) - 0x4B400000;        // rint(v*128), half-even
    return max(-128, min(127, q));
}

// modrelu + activation quantization (validated bit-exact in R8).
__device__ __forceinline__ int modrelu_q(int z, float bc128) {
    int az = abs(z);                                 // az < 2^19
    float azf = __int_as_float(0x4B000000 + az);     // 2^23 + az, exact
    float t8  = azf * 0.125f;                        // 2^20 + az/8, exact
    float f   = t8 - 1048576.0f;                     // az/8, exact
    float g   = f + bc128;                           // single RN (== ref)
    float m   = fmaxf(g, 0.0f);
    float tm  = m + 12582912.0f;                     // round half-even
    int ni    = __float_as_int(tm) - 0x4B400000;
    int s     = z >> 31;
    int t2    = min(ni, 127 - s);
    int r     = (t2 ^ s) - s;
    int nz    = (z | -z) >> 31;
    return r & nz;
}

// D += A(16x32 s8, row-major) * B(32x8 s8, col-major), s32 accum (exact).
__device__ __forceinline__ void mma_s8(int* d, const uint32_t* a,
                                       uint32_t b0, uint32_t b1) {
    asm volatile(
        "mma.sync.aligned.m16n8k32.row.col.s32.s8.s8.s32 "
        "{%0,%1,%2,%3}, {%4,%5,%6,%7}, {%8,%9}, {%0,%1,%2,%3};"
        : "+r"(d[0]), "+r"(d[1]), "+r"(d[2]), "+r"(d[3])
        : "r"(a[0]), "r"(a[1]), "r"(a[2]), "r"(a[3]), "r"(b0), "r"(b1));
}

// Scan: one CTA = 8 batch rows (mma N dim), 256 threads, grid 32, 1 CTA/SM.
__global__ __launch_bounds__(256, 1)
void qornn_kernel(const float* __restrict__ x,
                  const float* __restrict__ b,
                  float* __restrict__ out) {
    __shared__ uint32_t sh_h[2][8 * HSTR];   // ping-pong h: 8 rows x 256 int8 (padded)
    __shared__ uint32_t sh_x[2][8 * XSTR];   // ping-pong xq: 8 rows x 64 int8 (padded)

    const int tid  = threadIdx.x;
    const int w    = tid >> 5;       // warp 0..7 -> units [32w, 32w+32)
    const int lane = tid & 31;
    const int g    = lane >> 2;      // row-group / B-column (n)
    const int tg   = lane & 3;       // k sub-group
    const int r0   = blockIdx.x * 8;

    // A fragments, register-resident.
    // m16n8k32 s8 layout: a0=(row g, k 4tg..+3), a1=(row g+8, same k),
    // a2=(row g, k+16), a3=(row g+8, k+16).  k-tile kt covers k=32kt..32kt+31.
    uint32_t aWr[2][8][4];
    uint32_t aWi[2][2][4];
#pragma unroll
    for (int m = 0; m < 2; m++) {
        const int u0 = w * 32 + m * 16 + g;
#pragma unroll
        for (int kt = 0; kt < 8; kt++) {
            aWr[m][kt][0] = g_WrP[u0 * 64 + kt * 8 + tg];
            aWr[m][kt][1] = g_WrP[(u0 + 8) * 64 + kt * 8 + tg];
            aWr[m][kt][2] = g_WrP[u0 * 64 + kt * 8 + tg + 4];
            aWr[m][kt][3] = g_WrP[(u0 + 8) * 64 + kt * 8 + tg + 4];
        }
#pragma unroll
        for (int kt = 0; kt < 2; kt++) {
            aWi[m][kt][0] = g_WiP[u0 * 16 + kt * 8 + tg];
            aWi[m][kt][1] = g_WiP[(u0 + 8) * 16 + kt * 8 + tg];
            aWi[m][kt][2] = g_WiP[u0 * 16 + kt * 8 + tg + 4];
            aWi[m][kt][3] = g_WiP[(u0 + 8) * 16 + kt * 8 + tg + 4];
        }
    }
    // Bias for the units this lane's C fragment holds (rows g, g+8 per M-tile).
    float bb[2][2];
    bb[0][0] = b[w * 32 + g]      * 128.0f;
    bb[0][1] = b[w * 32 + 8 + g]  * 128.0f;
    bb[1][0] = b[w * 32 + 16 + g] * 128.0f;
    bb[1][1] = b[w * 32 + 24 + g] * 128.0f;

    // h0 = 0 (both buffers incl. padding)
    for (int i = tid; i < 2 * 8 * HSTR; i += 256) ((uint32_t*)sh_h)[i] = 0u;

    // x producers: thread handles global idx {tid, tid+256} of 512 (8 rows x 64).
    const int xr0 = tid >> 6;            // row 0..3
    const int xr1 = xr0 + 4;             // row 4..7
    const int xf  = tid & 63;            // feature
    const float* xb0 = x + (size_t)(r0 + xr0) * (TT * NI) + xf;
    const float* xb1 = x + (size_t)(r0 + xr1) * (TT * NI) + xf;

    // Stage xq(t=0); hold x(1), x(2) in a 2-deep register pipeline.
    ((int8_t*)sh_x[0])[xr0 * (XSTR * 4) + xf] = (int8_t)quant8(xb0[0]);
    ((int8_t*)sh_x[0])[xr1 * (XSTR * 4) + xf] = (int8_t)quant8(xb1[0]);
    float xa0 = xb0[1 * NI], xa1 = xb1[1 * NI];   // for t=1
    float xc0 = xb0[2 * NI], xc1 = xb1[2 * NI];   // for t=2
    __syncthreads();

    // B-frag word offsets: n = g, k-word = kt*8 + tg (+4 for hi half).
    const int hoff = g * HSTR + tg;
    const int xoff = g * XSTR + tg;

    for (int t = 0; t < TT; t++) {
        const int cur = t & 1;
        const uint32_t* hb = sh_h[cur];
        const uint32_t* xw = sh_x[cur];

        // Stage xq(t+1) (held regs) into the next buffer; advance pipeline.
        ((int8_t*)sh_x[cur ^ 1])[xr0 * (XSTR * 4) + xf] = (int8_t)quant8(xa0);
        ((int8_t*)sh_x[cur ^ 1])[xr1 * (XSTR * 4) + xf] = (int8_t)quant8(xa1);
        xa0 = xc0; xa1 = xc1;
        const int tn = (t + 3 < TT) ? t + 3 : TT - 1;
        xc0 = __ldcs(xb0 + (size_t)tn * NI);
        xc1 = __ldcs(xb1 + (size_t)tn * NI);

        int acc[2][2][4] = {};   // [M-tile][chain][frag]

        // Recurrent part: K = 256 over sh_h.
#pragma unroll
        for (int kt = 0; kt < 8; kt++) {
            uint32_t b0 = hb[hoff + kt * 8];
            uint32_t b1 = hb[hoff + kt * 8 + 4];
            mma_s8(acc[0][kt & 1], aWr[0][kt], b0, b1);
            mma_s8(acc[1][kt & 1], aWr[1][kt], b0, b1);
        }
        // Input part: K = 64 over sh_x.
#pragma unroll
        for (int kt = 0; kt < 2; kt++) {
            uint32_t b0 = xw[xoff + kt * 8];
            uint32_t b1 = xw[xoff + kt * 8 + 4];
            mma_s8(acc[0][kt], aWi[0][kt], b0, b1);
            mma_s8(acc[1][kt], aWi[1][kt], b0, b1);
        }

        // Epilogue: C layout c_j: j0=(row g, col 2tg), j1=(g, 2tg+1),
        // j2=(g+8, 2tg), j3=(g+8, 2tg+1). unit = base + (j>>1)*8; batchrow = col.
        int8_t* hn = (int8_t*)sh_h[cur ^ 1];
#pragma unroll
        for (int m = 0; m < 2; m++) {
            const int ub = w * 32 + m * 16 + g;
#pragma unroll
            for (int j = 0; j < 4; j++) {
                int z = acc[m][0][j] + acc[m][1][j];
                int unit = ub + ((j >> 1) << 3);
                int row = 2 * tg + (j & 1);
                hn[row * (HSTR * 4) + unit] = (int8_t)modrelu_q(z, bb[m][j >> 1]);
            }
        }
        __syncthreads();
    }

    // Output head: h_last in buffer 0 (t=1023: cur=1 wrote 0). 8 rows x 16 outs.
    if (tid < 128) {
        const int row = tid >> 4;
        const int o = tid & 15;
        const uint32_t* hrow = sh_h[0] + row * HSTR;
        int acc = 0;
#pragma unroll
        for (int kw = 0; kw < 64; kw++)
            acc = __dp4a((int)hrow[kw], (int)g_WoP[o * 64 + kw], acc);
        out[(r0 + row) * NO + o] = (float)acc * (1.0f / 1024.0f);
    }
}

extern "C" void kernel_launch(void* const* d_in, const int* in_sizes, int n_in,
                              void* d_out, int out_size) {
    const float* inputs = (const float*)d_in[0];  // [256,1024,64]
    const float* Wi     = (const float*)d_in[1];  // [256,64]
    const float* Wr     = (const float*)d_in[2];  // [256,256]
    const float* Wo     = (const float*)d_in[3];  // [16,256]
    const float* b      = (const float*)d_in[4];  // [256]
    float* out = (float*)d_out;                   // [256,16]

    prep_kernel<<<(NPACK + 255) / 256, 256>>>(Wi, Wr, Wo);
    qornn_kernel<<<NB / 8, 256>>>(inputs, b, out);
}